// round 3
// baseline (speedup 1.0000x reference)
#include <cuda_runtime.h>
#include <math.h>

#define KNN 20
#define NPTS 8192
typedef unsigned long long ull;

// ---------------- scratch ----------------
__device__ __align__(256) float g_feat[NPTS * 192];
__device__ __align__(256) float g_u[NPTS * 64];
__device__ __align__(256) float g_v[NPTS * 64];
__device__ __align__(256) int   g_idx[NPTS * KNN];
__device__ __align__(256) float g_h1[NPTS * 1024];
__device__ __align__(256) float g_h2[NPTS * 256];
__device__ __align__(256) float g_h3[NPTS * 128];

__device__ __forceinline__ void fma2(ull& d, ull a, ull b) {
    asm("fma.rn.f32x2 %0, %1, %2, %0;" : "+l"(d) : "l"(a), "l"(b));
}
__device__ __forceinline__ float sum2(ull u) {
    return __uint_as_float((unsigned)u) + __uint_as_float((unsigned)(u >> 32));
}

// ---------------- unified GEMM-tiled kNN ----------------
// 256 thr, 64 query rows per block, 256-candidate tiles, 8x8 f32x2 micro-tile.
// Selection straight from registers: warp ty owns rows {ty*4..+3, 32+ty*4..+3};
// lane tx holds cols {ch*64 + tx*2, +1}. Top-20 list distributed on lanes 0..19.
// KP = k-pairs (C3=true pads 3 dims to 2 pairs).
template<int KP, bool C3>
__global__ void __launch_bounds__(256, 1)
knn_f2_kernel(const float* __restrict__ X, int ldx,
              int* __restrict__ idx, int N)
{
    extern __shared__ float sh[];
    float2* Qs2 = (float2*)sh;               // [KP][64]
    float2* Cs2 = Qs2 + KP * 64;             // [KP][256]
    float*  sSq = (float*)(Cs2 + KP * 256);  // [256]

    const int tid = threadIdx.x;
    const int ty  = tid >> 5;
    const int tx  = tid & 31;
    const int rowBase = blockIdx.x * 64;

    // --- load Q tile ---
    if (C3) {
        if (tid < 64) {
            int r = tid;
            const float* xr = X + (rowBase + r) * ldx;
            float a = xr[0], b = xr[1], c = xr[2];
            Qs2[0 * 64 + r] = make_float2(a, b);
            Qs2[1 * 64 + r] = make_float2(c, 0.f);
        }
    } else {
        int r  = tid >> 2;
        int cq = (tid & 3) * 16;
        const float* xr = X + (rowBase + r) * ldx + cq;
        #pragma unroll
        for (int q = 0; q < 4; q++) {
            float4 v = *(const float4*)(xr + q * 4);
            int kp = (cq >> 1) + q * 2;
            Qs2[(kp + 0) * 64 + r] = make_float2(v.x, v.y);
            Qs2[(kp + 1) * 64 + r] = make_float2(v.z, v.w);
        }
    }

    // --- per-row top-k state ---
    float bestd[8], wv[8];
    int   bestj[8];
    #pragma unroll
    for (int m = 0; m < 8; m++) {
        bestd[m] = (tx < KNN) ? INFINITY : -INFINITY;
        bestj[m] = 0x7fffffff;
        wv[m]    = INFINITY;
    }

    for (int base = 0; base < N; base += 256) {
        __syncthreads();   // protect previous tile's Cs2/sSq reads
        // --- load candidate tile + inline norms ---
        if (C3) {
            const float* xr = X + (base + tid) * ldx;
            float a = xr[0], b = xr[1], c = xr[2];
            Cs2[0 * 256 + tid] = make_float2(a, b);
            Cs2[1 * 256 + tid] = make_float2(c, 0.f);
            sSq[tid] = fmaf(a, a, fmaf(b, b, c * c));
        } else {
            const float* xr = X + (base + tid) * ldx;
            float sq = 0.f;
            #pragma unroll
            for (int q = 0; q < 16; q++) {
                float4 v = *(const float4*)(xr + q * 4);
                Cs2[(2 * q + 0) * 256 + tid] = make_float2(v.x, v.y);
                Cs2[(2 * q + 1) * 256 + tid] = make_float2(v.z, v.w);
                sq = fmaf(v.x, v.x, sq); sq = fmaf(v.y, v.y, sq);
                sq = fmaf(v.z, v.z, sq); sq = fmaf(v.w, v.w, sq);
            }
            sSq[tid] = sq;
        }
        __syncthreads();

        // --- GEMM ---
        ull acc[8][8];
        #pragma unroll
        for (int m = 0; m < 8; m++)
            #pragma unroll
            for (int n = 0; n < 8; n++) acc[m][n] = 0ull;

        #pragma unroll (KP > 8 ? 4 : KP)
        for (int kp = 0; kp < KP; kp++) {
            ull a[8], b[8];
            const ulonglong2* pa0 = (const ulonglong2*)(Qs2 + kp * 64 + ty * 4);
            const ulonglong2* pa1 = (const ulonglong2*)(Qs2 + kp * 64 + 32 + ty * 4);
            ulonglong2 A0 = pa0[0], A1 = pa0[1], A2 = pa1[0], A3 = pa1[1];
            a[0] = A0.x; a[1] = A0.y; a[2] = A1.x; a[3] = A1.y;
            a[4] = A2.x; a[5] = A2.y; a[6] = A3.x; a[7] = A3.y;
            #pragma unroll
            for (int ch = 0; ch < 4; ch++) {
                ulonglong2 B = *(const ulonglong2*)(Cs2 + kp * 256 + ch * 64 + tx * 2);
                b[2 * ch] = B.x; b[2 * ch + 1] = B.y;
            }
            #pragma unroll
            for (int m = 0; m < 8; m++)
                #pragma unroll
                for (int n = 0; n < 8; n++)
                    fma2(acc[m][n], a[m], b[n]);
        }

        // --- per-row selection from registers ---
        #pragma unroll
        for (int m = 0; m < 8; m++) {
            int row  = (m < 4) ? (ty * 4 + m) : (32 + ty * 4 + (m - 4));
            int grow = rowBase + row;

            float dv[8];
            bool  pass[8];
            bool  any = false;
            #pragma unroll
            for (int ch = 0; ch < 4; ch++) {
                float2 s2 = *(const float2*)&sSq[ch * 64 + tx * 2];
                dv[2 * ch]     = s2.x - 2.f * sum2(acc[m][2 * ch]);
                dv[2 * ch + 1] = s2.y - 2.f * sum2(acc[m][2 * ch + 1]);
                int j0 = base + ch * 64 + tx * 2;
                pass[2 * ch]     = (dv[2 * ch]     < wv[m]) && (j0     != grow);
                pass[2 * ch + 1] = (dv[2 * ch + 1] < wv[m]) && (j0 + 1 != grow);
                any = any || pass[2 * ch] || pass[2 * ch + 1];
            }
            if (__ballot_sync(~0u, any) == 0) continue;

            #pragma unroll
            for (int ch = 0; ch < 4; ch++) {
                #pragma unroll
                for (int p = 0; p < 2; p++) {
                    int q = 2 * ch + p;
                    bool ps = (dv[q] < wv[m]) && (base + ch * 64 + tx * 2 + p != grow);
                    unsigned mask = __ballot_sync(~0u, ps);
                    while (mask) {
                        int src = __ffs(mask) - 1; mask &= mask - 1;
                        float dd = __shfl_sync(~0u, dv[q], src);
                        if (dd >= wv[m]) continue;
                        int jj = base + ch * 64 + 2 * src + p;
                        // evict: lane holding the current worst
                        unsigned em = __ballot_sync(~0u, bestd[m] == wv[m]);
                        int evl;
                        if (__popc(em) == 1) {
                            evl = __ffs(em) - 1;
                        } else {
                            // rare tie: evict the entry with largest index
                            evl = -1; int mx = -1;
                            unsigned t = em;
                            while (t) {
                                int l = __ffs(t) - 1; t &= t - 1;
                                int jv = __shfl_sync(~0u, bestj[m], l);
                                if (jv > mx) { mx = jv; evl = l; }
                            }
                        }
                        if (tx == evl) { bestd[m] = dd; bestj[m] = jj; }
                        float v = bestd[m];
                        #pragma unroll
                        for (int off = 16; off; off >>= 1)
                            v = fmaxf(v, __shfl_xor_sync(~0u, v, off));
                        wv[m] = v;
                    }
                }
            }
        }
    }

    #pragma unroll
    for (int m = 0; m < 8; m++) {
        int row = (m < 4) ? (ty * 4 + m) : (32 + ty * 4 + (m - 4));
        if (tx < KNN)
            idx[(rowBase + row) * KNN + tx] = bestj[m];
    }
}

// ---------------- EdgeConv U/V ----------------
template<int C>
__global__ void uv_kernel(const float* __restrict__ X, int ldx,
                          const float* __restrict__ w,
                          float* __restrict__ U, float* __restrict__ V, int N)
{
    __shared__ float sw[2 * C * 64];
    __shared__ float sx[4][C > 0 ? C : 1];
    int tid = threadIdx.y * 64 + threadIdx.x;
    for (int t = tid; t < 2 * C * 64; t += 256) sw[t] = w[t];
    int i = blockIdx.x * 4 + threadIdx.y;
    for (int c = threadIdx.x; c < C; c += 64) sx[threadIdx.y][c] = X[i * ldx + c];
    __syncthreads();

    int f = threadIdx.x;
    float u = 0.f, v = 0.f;
    #pragma unroll
    for (int c = 0; c < C; c++) {
        float xc = sx[threadIdx.y][c];
        u = fmaf(xc, sw[c * 64 + f], u);
        v = fmaf(xc, sw[(C + c) * 64 + f], v);
    }
    U[i * 64 + f] = u - v;
    V[i * 64 + f] = v;
}

// ---------------- neighbor gather-max + relu ----------------
__global__ void edge_max_kernel(const float* __restrict__ U, const float* __restrict__ V,
                                const float* __restrict__ b, const int* __restrict__ idx,
                                float* __restrict__ out, int ldo, int colofs, int N)
{
    __shared__ int sidx[4][KNN];
    int i = blockIdx.x * 4 + threadIdx.y;
    if (threadIdx.x < KNN) sidx[threadIdx.y][threadIdx.x] = idx[i * KNN + threadIdx.x];
    __syncthreads();

    int f = threadIdx.x;
    float m = -INFINITY;
    #pragma unroll
    for (int t = 0; t < KNN; t++) {
        int j = sidx[threadIdx.y][t];
        m = fmaxf(m, V[j * 64 + f]);
    }
    float val = U[i * 64 + f] + b[f] + m;
    out[i * ldo + colofs + f] = fmaxf(val, 0.f);
}

// ---------------- f32x2 SGEMM 64x256, fused bias+relu ----------------
__global__ void __launch_bounds__(256, 1)
gemm_f2_64x256(const float* __restrict__ A, int lda,
               const float* __restrict__ B, int ldb,
               const float* __restrict__ bias,
               float* __restrict__ C, int ldc, int K)
{
    __shared__ float2 As2[16][64];
    __shared__ float2 Bs2[16][256];

    const int tid = threadIdx.x;
    const int ty  = tid >> 5, tx = tid & 31;
    const int rowBase = blockIdx.y * 64;
    const int colBase = blockIdx.x * 256;

    ull acc[8][8];
    #pragma unroll
    for (int m = 0; m < 8; m++)
        #pragma unroll
        for (int n = 0; n < 8; n++) acc[m][n] = 0ull;

    const int ar = tid >> 2, ac = (tid & 3) * 8;
    const int bkp = tid >> 4, bc0 = (tid & 15) * 4;

    for (int k0 = 0; k0 < K; k0 += 32) {
        float4 v0 = *(const float4*)&A[(rowBase + ar) * lda + k0 + ac];
        float4 v1 = *(const float4*)&A[(rowBase + ar) * lda + k0 + ac + 4];
        float4 blo[4], bhi[4];
        #pragma unroll
        for (int rep = 0; rep < 4; rep++) {
            int col = colBase + rep * 64 + bc0;
            blo[rep] = *(const float4*)&B[(k0 + 2 * bkp) * ldb + col];
            bhi[rep] = *(const float4*)&B[(k0 + 2 * bkp + 1) * ldb + col];
        }
        __syncthreads();
        As2[(ac >> 1) + 0][ar] = make_float2(v0.x, v0.y);
        As2[(ac >> 1) + 1][ar] = make_float2(v0.z, v0.w);
        As2[(ac >> 1) + 2][ar] = make_float2(v1.x, v1.y);
        As2[(ac >> 1) + 3][ar] = make_float2(v1.z, v1.w);
        #pragma unroll
        for (int rep = 0; rep < 4; rep++) {
            int c = rep * 64 + bc0;
            Bs2[bkp][c + 0] = make_float2(blo[rep].x, bhi[rep].x);
            Bs2[bkp][c + 1] = make_float2(blo[rep].y, bhi[rep].y);
            Bs2[bkp][c + 2] = make_float2(blo[rep].z, bhi[rep].z);
            Bs2[bkp][c + 3] = make_float2(blo[rep].w, bhi[rep].w);
        }
        __syncthreads();

        #pragma unroll 4
        for (int kp = 0; kp < 16; kp++) {
            ull a[8], b[8];
            const ulonglong2* pa0 = (const ulonglong2*)(&As2[kp][ty * 4]);
            const ulonglong2* pa1 = (const ulonglong2*)(&As2[kp][32 + ty * 4]);
            ulonglong2 A0 = pa0[0], A1 = pa0[1], A2 = pa1[0], A3 = pa1[1];
            a[0] = A0.x; a[1] = A0.y; a[2] = A1.x; a[3] = A1.y;
            a[4] = A2.x; a[5] = A2.y; a[6] = A3.x; a[7] = A3.y;
            #pragma unroll
            for (int ch = 0; ch < 4; ch++) {
                ulonglong2 Bv = *(const ulonglong2*)(&Bs2[kp][ch * 64 + tx * 2]);
                b[2 * ch] = Bv.x; b[2 * ch + 1] = Bv.y;
            }
            #pragma unroll
            for (int m = 0; m < 8; m++)
                #pragma unroll
                for (int n = 0; n < 8; n++)
                    fma2(acc[m][n], a[m], b[n]);
        }
    }

    #pragma unroll
    for (int m = 0; m < 8; m++) {
        int row = rowBase + ((m < 4) ? (ty * 4 + m) : (32 + ty * 4 + (m - 4)));
        #pragma unroll
        for (int ch = 0; ch < 4; ch++) {
            int col = colBase + ch * 64 + tx * 2;
            float d0 = fmaxf(sum2(acc[m][2 * ch])     + bias[col],     0.f);
            float d1 = fmaxf(sum2(acc[m][2 * ch + 1]) + bias[col + 1], 0.f);
            *(float2*)&C[row * ldc + col] = make_float2(d0, d1);
        }
    }
}

// ---------------- small SGEMM (wm2) ----------------
__global__ void sgemm_bias_relu(const float* __restrict__ A, int lda,
                                const float* __restrict__ B, int ldb,
                                const float* __restrict__ bias,
                                float* __restrict__ Cm, int ldc,
                                int Kdim, int relu)
{
    __shared__ float As[16][68];
    __shared__ float Bs[16][64];
    const int tid = threadIdx.x;
    const int tx = tid & 15, ty = tid >> 4;
    const int rowBase = blockIdx.y * 64;
    const int colBase = blockIdx.x * 64;

    const int ar = tid >> 2, akq = (tid & 3) * 4;
    const int bk = tid >> 4, bc = (tid & 15) * 4;

    float acc[4][4] = {};
    for (int k0 = 0; k0 < Kdim; k0 += 16) {
        float4 av = *(const float4*)&A[(rowBase + ar) * lda + k0 + akq];
        float4 bv = *(const float4*)&B[(k0 + bk) * ldb + colBase + bc];
        __syncthreads();
        As[akq + 0][ar] = av.x; As[akq + 1][ar] = av.y;
        As[akq + 2][ar] = av.z; As[akq + 3][ar] = av.w;
        *(float4*)&Bs[bk][bc] = bv;
        __syncthreads();
        #pragma unroll
        for (int kk = 0; kk < 16; kk++) {
            float a[4], bb[4];
            #pragma unroll
            for (int m = 0; m < 4; m++) a[m] = As[kk][ty * 4 + m];
            #pragma unroll
            for (int n = 0; n < 4; n++) bb[n] = Bs[kk][tx * 4 + n];
            #pragma unroll
            for (int m = 0; m < 4; m++)
                #pragma unroll
                for (int n = 0; n < 4; n++)
                    acc[m][n] = fmaf(a[m], bb[n], acc[m][n]);
        }
    }
    #pragma unroll
    for (int m = 0; m < 4; m++) {
        int r = rowBase + ty * 4 + m;
        #pragma unroll
        for (int n = 0; n < 4; n++) {
            int c = colBase + tx * 4 + n;
            float v = acc[m][n] + bias[c];
            if (relu) v = fmaxf(v, 0.f);
            Cm[r * ldc + c] = v;
        }
    }
}

// ---------------- final 128->13 + log_softmax ----------------
__global__ void final_logsoftmax(const float* __restrict__ H,
                                 const float* __restrict__ W,
                                 const float* __restrict__ b,
                                 float* __restrict__ out, int N)
{
    __shared__ float sw[128 * 13];
    __shared__ float sb[13];
    int tid = threadIdx.x;
    for (int t = tid; t < 128 * 13; t += 256) sw[t] = W[t];
    if (tid < 13) sb[tid] = b[tid];
    __syncthreads();

    int warp = tid >> 5, lane = tid & 31;
    int i = blockIdx.x * 8 + warp;

    float h[4];
    #pragma unroll
    for (int q = 0; q < 4; q++) h[q] = H[i * 128 + q * 32 + lane];

    float z[13];
    #pragma unroll
    for (int f = 0; f < 13; f++) {
        float acc = 0.f;
        #pragma unroll
        for (int q = 0; q < 4; q++)
            acc = fmaf(h[q], sw[(q * 32 + lane) * 13 + f], acc);
        #pragma unroll
        for (int off = 16; off; off >>= 1)
            acc += __shfl_xor_sync(~0u, acc, off);
        z[f] = acc + sb[f];
    }
    float m = z[0];
    #pragma unroll
    for (int f = 1; f < 13; f++) m = fmaxf(m, z[f]);
    float s = 0.f;
    #pragma unroll
    for (int f = 0; f < 13; f++) s += expf(z[f] - m);
    float lse = m + logf(s);
    if (lane == 0) {
        #pragma unroll
        for (int f = 0; f < 13; f++) out[i * 13 + f] = z[f] - lse;
    }
}

// ---------------- launch ----------------
extern "C" void kernel_launch(void* const* d_in, const int* in_sizes, int n_in,
                              void* d_out, int out_size)
{
    const float* x   = (const float*)d_in[0];
    const float* w1  = (const float*)d_in[1];
    const float* b1  = (const float*)d_in[2];
    const float* w2  = (const float*)d_in[3];
    const float* b2  = (const float*)d_in[4];
    const float* w3  = (const float*)d_in[5];
    const float* b3  = (const float*)d_in[6];
    const float* wl1 = (const float*)d_in[7];
    const float* bl1 = (const float*)d_in[8];
    const float* wm1 = (const float*)d_in[9];
    const float* bm1 = (const float*)d_in[10];
    const float* wm2 = (const float*)d_in[11];
    const float* bm2 = (const float*)d_in[12];
    const float* wm3 = (const float*)d_in[13];
    const float* bm3 = (const float*)d_in[14];
    float* out = (float*)d_out;
    const int N = NPTS;

    float *feat, *u, *v, *h1, *h2, *h3; int* idx;
    cudaGetSymbolAddress((void**)&feat, g_feat);
    cudaGetSymbolAddress((void**)&u,    g_u);
    cudaGetSymbolAddress((void**)&v,    g_v);
    cudaGetSymbolAddress((void**)&idx,  g_idx);
    cudaGetSymbolAddress((void**)&h1,   g_h1);
    cudaGetSymbolAddress((void**)&h2,   g_h2);
    cudaGetSymbolAddress((void**)&h3,   g_h3);

    const size_t shK2  = 2  * 64 * 8 + 2  * 256 * 8 + 256 * 4;   //  6.1 KB
    const size_t shK32 = 32 * 64 * 8 + 32 * 256 * 8 + 256 * 4;   // 83.0 KB
    cudaFuncSetAttribute((const void*)knn_f2_kernel<32, false>,
                         cudaFuncAttributeMaxDynamicSharedMemorySize, (int)shK32);

    dim3 b64x4(64, 4);

    // ---- layer 1 (C=3, padded to 2 k-pairs) ----
    knn_f2_kernel<2, true><<<N / 64, 256, shK2>>>(x, 3, idx, N);
    uv_kernel<3><<<N / 4, b64x4>>>(x, 3, w1, u, v, N);
    edge_max_kernel<<<N / 4, b64x4>>>(u, v, b1, idx, feat, 192, 0, N);

    // ---- layer 2 (C=64 on feat[:,0:64]) ----  (knn64 = 4th launch -> ncu slot)
    knn_f2_kernel<32, false><<<N / 64, 256, shK32>>>(feat, 192, idx, N);
    uv_kernel<64><<<N / 4, b64x4>>>(feat, 192, w2, u, v, N);
    edge_max_kernel<<<N / 4, b64x4>>>(u, v, b2, idx, feat, 192, 64, N);

    // ---- layer 3 (C=64 on feat[:,64:128]) ----
    knn_f2_kernel<32, false><<<N / 64, 256, shK32>>>(feat + 64, 192, idx, N);
    uv_kernel<64><<<N / 4, b64x4>>>(feat + 64, 192, w3, u, v, N);
    edge_max_kernel<<<N / 4, b64x4>>>(u, v, b3, idx, feat, 192, 128, N);

    // ---- MLP head ----
    gemm_f2_64x256<<<dim3(4, 128), 256>>>(feat, 192, wl1, 1024, bl1, h1, 1024, 192);
    gemm_f2_64x256<<<dim3(1, 128), 256>>>(h1, 1024, wm1, 256, bm1, h2, 256, 1024);
    sgemm_bias_relu<<<dim3(2, 128), 256>>>(h2, 256, wm2, 128, bm2, h3, 128, 256, 1);
    final_logsoftmax<<<N / 8, 256>>>(h3, wm3, bm3, out, N);
}

// round 4
// speedup vs baseline: 1.4267x; 1.4267x over previous
#include <cuda_runtime.h>
#include <math.h>

#define KNN 20
#define NPTS 8192
typedef unsigned long long ull;

// ---------------- scratch ----------------
__device__ __align__(256) float g_feat[NPTS * 192];
__device__ __align__(256) float g_u[NPTS * 64];
__device__ __align__(256) float g_v[NPTS * 64];
__device__ __align__(256) int   g_idx[NPTS * KNN];
__device__ __align__(256) float g_h1[NPTS * 1024];
__device__ __align__(256) float g_h2[NPTS * 256];
__device__ __align__(256) float g_h3[NPTS * 128];

__device__ __forceinline__ void fma2(ull& d, ull a, ull b) {
    asm("fma.rn.f32x2 %0, %1, %2, %0;" : "+l"(d) : "l"(a), "l"(b));
}
__device__ __forceinline__ float sum2(ull u) {
    return __uint_as_float((unsigned)u) + __uint_as_float((unsigned)(u >> 32));
}

// ---------------- fused kNN: f32x2 GEMM + per-thread private top-20 ----------------
// 256 thr, 64 query rows/block, 256-candidate tiles, 8x8 f32x2 micro-tile.
// Distances staged to shared; thread (r=tid>>2, q=tid&3) owns the q-th quarter
// (64 cols) of row r and keeps an exact private top-20 of its 2048-candidate
// subset in a 21-strided shared list (conflict-free, no warp cooperation).
// Tail: thread q==0 merges the row's 4 lists (20-of-80 selection).
#define SD_STRIDE 264   // row stride in floats
#define SD_QOFS   66    // quarter offset in floats
template<int KP, bool C3>
__global__ void __launch_bounds__(256, 1)
knn_sel_kernel(const float* __restrict__ X, int ldx,
               int* __restrict__ idx, int N)
{
    extern __shared__ float sh[];
    float2* Qs2   = (float2*)sh;                    // [KP][64]
    float2* Cs2   = Qs2 + KP * 64;                  // [KP][256]
    float*  sSq   = (float*)(Cs2 + KP * 256);       // [256]
    float*  sDist = sSq + 256;                      // [64][264]
    float*  Ld    = sDist + 64 * SD_STRIDE;         // [256][21]
    int*    Lj    = (int*)(Ld + 256 * 21);          // [256][21]

    const int tid = threadIdx.x;
    const int ty  = tid >> 5;
    const int tx  = tid & 31;
    const int rowBase = blockIdx.x * 64;

    // --- load Q tile ---
    if (C3) {
        if (tid < 64) {
            int r = tid;
            const float* xr = X + (rowBase + r) * ldx;
            float a = xr[0], b = xr[1], c = xr[2];
            Qs2[0 * 64 + r] = make_float2(a, b);
            Qs2[1 * 64 + r] = make_float2(c, 0.f);
        }
    } else {
        int r  = tid >> 2;
        int cq = (tid & 3) * 16;
        const float* xr = X + (rowBase + r) * ldx + cq;
        #pragma unroll
        for (int q = 0; q < 4; q++) {
            float4 v = *(const float4*)(xr + q * 4);
            int kp = (cq >> 1) + q * 2;
            Qs2[(kp + 0) * 64 + r] = make_float2(v.x, v.y);
            Qs2[(kp + 1) * 64 + r] = make_float2(v.z, v.w);
        }
    }

    // --- private top-k state ---
    const int selR = tid >> 2;          // row this thread selects for
    const int selQ = tid & 3;           // quarter of that row
    const int grow = rowBase + selR;
    float* myLd = Ld + tid * 21;
    int*   myLj = Lj + tid * 21;
    #pragma unroll
    for (int t = 0; t < KNN; t++) myLd[t] = INFINITY;
    float wd = INFINITY;
    int   wpos = 0;

    for (int base = 0; base < N; base += 256) {
        __syncthreads();   // selection done reading sDist; GEMM done reading Cs2
        // --- load candidate tile + inline norms ---
        if (C3) {
            const float* xr = X + (base + tid) * ldx;
            float a = xr[0], b = xr[1], c = xr[2];
            Cs2[0 * 256 + tid] = make_float2(a, b);
            Cs2[1 * 256 + tid] = make_float2(c, 0.f);
            sSq[tid] = fmaf(a, a, fmaf(b, b, c * c));
        } else {
            const float* xr = X + (base + tid) * ldx;
            float sq = 0.f;
            #pragma unroll
            for (int q = 0; q < 16; q++) {
                float4 v = *(const float4*)(xr + q * 4);
                Cs2[(2 * q + 0) * 256 + tid] = make_float2(v.x, v.y);
                Cs2[(2 * q + 1) * 256 + tid] = make_float2(v.z, v.w);
                sq = fmaf(v.x, v.x, sq); sq = fmaf(v.y, v.y, sq);
                sq = fmaf(v.z, v.z, sq); sq = fmaf(v.w, v.w, sq);
            }
            sSq[tid] = sq;
        }
        __syncthreads();

        // --- GEMM ---
        ull acc[8][8];
        #pragma unroll
        for (int m = 0; m < 8; m++)
            #pragma unroll
            for (int n = 0; n < 8; n++) acc[m][n] = 0ull;

        #pragma unroll (KP > 8 ? 4 : KP)
        for (int kp = 0; kp < KP; kp++) {
            ull a[8], b[8];
            const ulonglong2* pa0 = (const ulonglong2*)(Qs2 + kp * 64 + ty * 4);
            const ulonglong2* pa1 = (const ulonglong2*)(Qs2 + kp * 64 + 32 + ty * 4);
            ulonglong2 A0 = pa0[0], A1 = pa0[1], A2 = pa1[0], A3 = pa1[1];
            a[0] = A0.x; a[1] = A0.y; a[2] = A1.x; a[3] = A1.y;
            a[4] = A2.x; a[5] = A2.y; a[6] = A3.x; a[7] = A3.y;
            #pragma unroll
            for (int ch = 0; ch < 4; ch++) {
                ulonglong2 B = *(const ulonglong2*)(Cs2 + kp * 256 + ch * 64 + tx * 2);
                b[2 * ch] = B.x; b[2 * ch + 1] = B.y;
            }
            #pragma unroll
            for (int m = 0; m < 8; m++)
                #pragma unroll
                for (int n = 0; n < 8; n++)
                    fma2(acc[m][n], a[m], b[n]);
        }

        // --- epilogue: dist -> shared (quarter-padded layout) ---
        #pragma unroll
        for (int m = 0; m < 8; m++) {
            int row = (m < 4) ? (ty * 4 + m) : (32 + ty * 4 + (m - 4));
            #pragma unroll
            for (int ch = 0; ch < 4; ch++) {
                float2 s2 = *(const float2*)&sSq[ch * 64 + tx * 2];
                float d0 = s2.x - 2.f * sum2(acc[m][2 * ch]);
                float d1 = s2.y - 2.f * sum2(acc[m][2 * ch + 1]);
                *(float2*)&sDist[row * SD_STRIDE + ch * SD_QOFS + tx * 2] =
                    make_float2(d0, d1);
            }
        }
        __syncthreads();

        // --- selection: per-thread private scan of its 64-col quarter ---
        {
            const float* sp = sDist + selR * SD_STRIDE + selQ * SD_QOFS;
            const int jb = base + selQ * 64;
            #pragma unroll 4
            for (int o = 0; o < 64; o++) {
                float d = sp[o];
                if (d < wd && (jb + o) != grow) {
                    myLd[wpos] = d;
                    myLj[wpos] = jb + o;
                    wd = -INFINITY;
                    #pragma unroll
                    for (int t = 0; t < KNN; t++) {
                        float v = myLd[t];
                        if (v > wd) { wd = v; wpos = t; }
                    }
                }
            }
        }
    }

    __syncthreads();
    // --- tail merge: thread q==0 selects 20-of-80 for its row ---
    if (selQ == 0) {
        #pragma unroll 1
        for (int k = 0; k < KNN; k++) {
            float bd = INFINITY; int bj = 0x7fffffff;
            int bslot = 0;
            #pragma unroll 1
            for (int tt = 0; tt < 4; tt++) {
                int lb = (tid + tt) * 21;
                #pragma unroll 4
                for (int t = 0; t < KNN; t++) {
                    float d = Ld[lb + t];
                    if (d < bd) { bd = d; bj = Lj[lb + t]; bslot = lb + t; }
                }
            }
            Ld[bslot] = INFINITY;
            idx[grow * KNN + k] = bj;
        }
    }
}

// ---------------- EdgeConv U/V ----------------
template<int C>
__global__ void uv_kernel(const float* __restrict__ X, int ldx,
                          const float* __restrict__ w,
                          float* __restrict__ U, float* __restrict__ V, int N)
{
    __shared__ float sw[2 * C * 64];
    __shared__ float sx[4][C > 0 ? C : 1];
    int tid = threadIdx.y * 64 + threadIdx.x;
    for (int t = tid; t < 2 * C * 64; t += 256) sw[t] = w[t];
    int i = blockIdx.x * 4 + threadIdx.y;
    for (int c = threadIdx.x; c < C; c += 64) sx[threadIdx.y][c] = X[i * ldx + c];
    __syncthreads();

    int f = threadIdx.x;
    float u = 0.f, v = 0.f;
    #pragma unroll
    for (int c = 0; c < C; c++) {
        float xc = sx[threadIdx.y][c];
        u = fmaf(xc, sw[c * 64 + f], u);
        v = fmaf(xc, sw[(C + c) * 64 + f], v);
    }
    U[i * 64 + f] = u - v;
    V[i * 64 + f] = v;
}

// ---------------- neighbor gather-max + relu ----------------
__global__ void edge_max_kernel(const float* __restrict__ U, const float* __restrict__ V,
                                const float* __restrict__ b, const int* __restrict__ idx,
                                float* __restrict__ out, int ldo, int colofs, int N)
{
    __shared__ int sidx[4][KNN];
    int i = blockIdx.x * 4 + threadIdx.y;
    if (threadIdx.x < KNN) sidx[threadIdx.y][threadIdx.x] = idx[i * KNN + threadIdx.x];
    __syncthreads();

    int f = threadIdx.x;
    float m = -INFINITY;
    #pragma unroll
    for (int t = 0; t < KNN; t++) {
        int j = sidx[threadIdx.y][t];
        m = fmaxf(m, V[j * 64 + f]);
    }
    float val = U[i * 64 + f] + b[f] + m;
    out[i * ldo + colofs + f] = fmaxf(val, 0.f);
}

// ---------------- f32x2 SGEMM 64x256, fused bias+relu ----------------
__global__ void __launch_bounds__(256, 1)
gemm_f2_64x256(const float* __restrict__ A, int lda,
               const float* __restrict__ B, int ldb,
               const float* __restrict__ bias,
               float* __restrict__ C, int ldc, int K)
{
    __shared__ float2 As2[16][64];
    __shared__ float2 Bs2[16][256];

    const int tid = threadIdx.x;
    const int ty  = tid >> 5, tx = tid & 31;
    const int rowBase = blockIdx.y * 64;
    const int colBase = blockIdx.x * 256;

    ull acc[8][8];
    #pragma unroll
    for (int m = 0; m < 8; m++)
        #pragma unroll
        for (int n = 0; n < 8; n++) acc[m][n] = 0ull;

    const int ar = tid >> 2, ac = (tid & 3) * 8;
    const int bkp = tid >> 4, bc0 = (tid & 15) * 4;

    for (int k0 = 0; k0 < K; k0 += 32) {
        float4 v0 = *(const float4*)&A[(rowBase + ar) * lda + k0 + ac];
        float4 v1 = *(const float4*)&A[(rowBase + ar) * lda + k0 + ac + 4];
        float4 blo[4], bhi[4];
        #pragma unroll
        for (int rep = 0; rep < 4; rep++) {
            int col = colBase + rep * 64 + bc0;
            blo[rep] = *(const float4*)&B[(k0 + 2 * bkp) * ldb + col];
            bhi[rep] = *(const float4*)&B[(k0 + 2 * bkp + 1) * ldb + col];
        }
        __syncthreads();
        As2[(ac >> 1) + 0][ar] = make_float2(v0.x, v0.y);
        As2[(ac >> 1) + 1][ar] = make_float2(v0.z, v0.w);
        As2[(ac >> 1) + 2][ar] = make_float2(v1.x, v1.y);
        As2[(ac >> 1) + 3][ar] = make_float2(v1.z, v1.w);
        #pragma unroll
        for (int rep = 0; rep < 4; rep++) {
            int c = rep * 64 + bc0;
            Bs2[bkp][c + 0] = make_float2(blo[rep].x, bhi[rep].x);
            Bs2[bkp][c + 1] = make_float2(blo[rep].y, bhi[rep].y);
            Bs2[bkp][c + 2] = make_float2(blo[rep].z, bhi[rep].z);
            Bs2[bkp][c + 3] = make_float2(blo[rep].w, bhi[rep].w);
        }
        __syncthreads();

        #pragma unroll 4
        for (int kp = 0; kp < 16; kp++) {
            ull a[8], b[8];
            const ulonglong2* pa0 = (const ulonglong2*)(&As2[kp][ty * 4]);
            const ulonglong2* pa1 = (const ulonglong2*)(&As2[kp][32 + ty * 4]);
            ulonglong2 A0 = pa0[0], A1 = pa0[1], A2 = pa1[0], A3 = pa1[1];
            a[0] = A0.x; a[1] = A0.y; a[2] = A1.x; a[3] = A1.y;
            a[4] = A2.x; a[5] = A2.y; a[6] = A3.x; a[7] = A3.y;
            #pragma unroll
            for (int ch = 0; ch < 4; ch++) {
                ulonglong2 Bv = *(const ulonglong2*)(&Bs2[kp][ch * 64 + tx * 2]);
                b[2 * ch] = Bv.x; b[2 * ch + 1] = Bv.y;
            }
            #pragma unroll
            for (int m = 0; m < 8; m++)
                #pragma unroll
                for (int n = 0; n < 8; n++)
                    fma2(acc[m][n], a[m], b[n]);
        }
    }

    #pragma unroll
    for (int m = 0; m < 8; m++) {
        int row = rowBase + ((m < 4) ? (ty * 4 + m) : (32 + ty * 4 + (m - 4)));
        #pragma unroll
        for (int ch = 0; ch < 4; ch++) {
            int col = colBase + ch * 64 + tx * 2;
            float d0 = fmaxf(sum2(acc[m][2 * ch])     + bias[col],     0.f);
            float d1 = fmaxf(sum2(acc[m][2 * ch + 1]) + bias[col + 1], 0.f);
            *(float2*)&C[row * ldc + col] = make_float2(d0, d1);
        }
    }
}

// ---------------- small SGEMM (wm2) ----------------
__global__ void sgemm_bias_relu(const float* __restrict__ A, int lda,
                                const float* __restrict__ B, int ldb,
                                const float* __restrict__ bias,
                                float* __restrict__ Cm, int ldc,
                                int Kdim, int relu)
{
    __shared__ float As[16][68];
    __shared__ float Bs[16][64];
    const int tid = threadIdx.x;
    const int tx = tid & 15, ty = tid >> 4;
    const int rowBase = blockIdx.y * 64;
    const int colBase = blockIdx.x * 64;

    const int ar = tid >> 2, akq = (tid & 3) * 4;
    const int bk = tid >> 4, bc = (tid & 15) * 4;

    float acc[4][4] = {};
    for (int k0 = 0; k0 < Kdim; k0 += 16) {
        float4 av = *(const float4*)&A[(rowBase + ar) * lda + k0 + akq];
        float4 bv = *(const float4*)&B[(k0 + bk) * ldb + colBase + bc];
        __syncthreads();
        As[akq + 0][ar] = av.x; As[akq + 1][ar] = av.y;
        As[akq + 2][ar] = av.z; As[akq + 3][ar] = av.w;
        *(float4*)&Bs[bk][bc] = bv;
        __syncthreads();
        #pragma unroll
        for (int kk = 0; kk < 16; kk++) {
            float a[4], bb[4];
            #pragma unroll
            for (int m = 0; m < 4; m++) a[m] = As[kk][ty * 4 + m];
            #pragma unroll
            for (int n = 0; n < 4; n++) bb[n] = Bs[kk][tx * 4 + n];
            #pragma unroll
            for (int m = 0; m < 4; m++)
                #pragma unroll
                for (int n = 0; n < 4; n++)
                    acc[m][n] = fmaf(a[m], bb[n], acc[m][n]);
        }
    }
    #pragma unroll
    for (int m = 0; m < 4; m++) {
        int r = rowBase + ty * 4 + m;
        #pragma unroll
        for (int n = 0; n < 4; n++) {
            int c = colBase + tx * 4 + n;
            float v = acc[m][n] + bias[c];
            if (relu) v = fmaxf(v, 0.f);
            Cm[r * ldc + c] = v;
        }
    }
}

// ---------------- final 128->13 + log_softmax ----------------
__global__ void final_logsoftmax(const float* __restrict__ H,
                                 const float* __restrict__ W,
                                 const float* __restrict__ b,
                                 float* __restrict__ out, int N)
{
    __shared__ float sw[128 * 13];
    __shared__ float sb[13];
    int tid = threadIdx.x;
    for (int t = tid; t < 128 * 13; t += 256) sw[t] = W[t];
    if (tid < 13) sb[tid] = b[tid];
    __syncthreads();

    int warp = tid >> 5, lane = tid & 31;
    int i = blockIdx.x * 8 + warp;

    float h[4];
    #pragma unroll
    for (int q = 0; q < 4; q++) h[q] = H[i * 128 + q * 32 + lane];

    float z[13];
    #pragma unroll
    for (int f = 0; f < 13; f++) {
        float acc = 0.f;
        #pragma unroll
        for (int q = 0; q < 4; q++)
            acc = fmaf(h[q], sw[(q * 32 + lane) * 13 + f], acc);
        #pragma unroll
        for (int off = 16; off; off >>= 1)
            acc += __shfl_xor_sync(~0u, acc, off);
        z[f] = acc + sb[f];
    }
    float m = z[0];
    #pragma unroll
    for (int f = 1; f < 13; f++) m = fmaxf(m, z[f]);
    float s = 0.f;
    #pragma unroll
    for (int f = 0; f < 13; f++) s += expf(z[f] - m);
    float lse = m + logf(s);
    if (lane == 0) {
        #pragma unroll
        for (int f = 0; f < 13; f++) out[i * 13 + f] = z[f] - lse;
    }
}

// ---------------- launch ----------------
extern "C" void kernel_launch(void* const* d_in, const int* in_sizes, int n_in,
                              void* d_out, int out_size)
{
    const float* x   = (const float*)d_in[0];
    const float* w1  = (const float*)d_in[1];
    const float* b1  = (const float*)d_in[2];
    const float* w2  = (const float*)d_in[3];
    const float* b2  = (const float*)d_in[4];
    const float* w3  = (const float*)d_in[5];
    const float* b3  = (const float*)d_in[6];
    const float* wl1 = (const float*)d_in[7];
    const float* bl1 = (const float*)d_in[8];
    const float* wm1 = (const float*)d_in[9];
    const float* bm1 = (const float*)d_in[10];
    const float* wm2 = (const float*)d_in[11];
    const float* bm2 = (const float*)d_in[12];
    const float* wm3 = (const float*)d_in[13];
    const float* bm3 = (const float*)d_in[14];
    float* out = (float*)d_out;
    const int N = NPTS;

    float *feat, *u, *v, *h1, *h2, *h3; int* idx;
    cudaGetSymbolAddress((void**)&feat, g_feat);
    cudaGetSymbolAddress((void**)&u,    g_u);
    cudaGetSymbolAddress((void**)&v,    g_v);
    cudaGetSymbolAddress((void**)&idx,  g_idx);
    cudaGetSymbolAddress((void**)&h1,   g_h1);
    cudaGetSymbolAddress((void**)&h2,   g_h2);
    cudaGetSymbolAddress((void**)&h3,   g_h3);

    auto shKNN = [](int kp) {
        return (size_t)kp * 64 * 8 + (size_t)kp * 256 * 8 + 256 * 4
             + 64 * SD_STRIDE * 4 + 256 * 21 * 4 * 2;
    };
    const size_t shK2  = shKNN(2);    // ~114 KB
    const size_t shK32 = shKNN(32);   // ~189 KB
    cudaFuncSetAttribute((const void*)knn_sel_kernel<32, false>,
                         cudaFuncAttributeMaxDynamicSharedMemorySize, (int)shK32);
    cudaFuncSetAttribute((const void*)knn_sel_kernel<2, true>,
                         cudaFuncAttributeMaxDynamicSharedMemorySize, (int)shK2);

    dim3 b64x4(64, 4);

    // ---- layer 1 (C=3, padded to 2 k-pairs) ----
    knn_sel_kernel<2, true><<<N / 64, 256, shK2>>>(x, 3, idx, N);
    uv_kernel<3><<<N / 4, b64x4>>>(x, 3, w1, u, v, N);
    edge_max_kernel<<<N / 4, b64x4>>>(u, v, b1, idx, feat, 192, 0, N);

    // ---- layer 2 (C=64 on feat[:,0:64]) ----  (knn64 = 4th launch -> ncu slot)
    knn_sel_kernel<32, false><<<N / 64, 256, shK32>>>(feat, 192, idx, N);
    uv_kernel<64><<<N / 4, b64x4>>>(feat, 192, w2, u, v, N);
    edge_max_kernel<<<N / 4, b64x4>>>(u, v, b2, idx, feat, 192, 64, N);

    // ---- layer 3 (C=64 on feat[:,64:128]) ----
    knn_sel_kernel<32, false><<<N / 64, 256, shK32>>>(feat + 64, 192, idx, N);
    uv_kernel<64><<<N / 4, b64x4>>>(feat + 64, 192, w3, u, v, N);
    edge_max_kernel<<<N / 4, b64x4>>>(u, v, b3, idx, feat, 192, 128, N);

    // ---- MLP head ----
    gemm_f2_64x256<<<dim3(4, 128), 256>>>(feat, 192, wl1, 1024, bl1, h1, 1024, 192);
    gemm_f2_64x256<<<dim3(1, 128), 256>>>(h1, 1024, wm1, 256, bm1, h2, 256, 1024);
    sgemm_bias_relu<<<dim3(2, 128), 256>>>(h2, 256, wm2, 128, bm2, h3, 128, 256, 1);
    final_logsoftmax<<<N / 8, 256>>>(h3, wm3, bm3, out, N);
}